// round 4
// baseline (speedup 1.0000x reference)
#include <cuda_runtime.h>
#include <cstdint>
#include <climits>

#define BB 64
#define PP 8732
#define OO 50
#define CC 81

// ---------------- scratch (device globals; no allocs allowed) ----------------
__device__ unsigned long long g_bestprior[BB * OO];  // packed (iou_bits<<32)|(~p)
__device__ int    g_bti[BB * PP];    // best truth idx per prior
__device__ float  g_bto[BB * PP];    // best truth overlap per prior
__device__ int    g_conft[BB * PP];  // conf target per prior
__device__ float  g_cerank[BB * PP]; // ce for negatives, 0 for positives
__device__ int    g_numpos[BB];
__device__ double g_lossl;
__device__ double g_lossc;

// ---------------- K0: zero accumulators ----------------
__global__ void k0_zero() {
    int i = blockIdx.x * blockDim.x + threadIdx.x;
    if (i < BB * OO) g_bestprior[i] = 0ull;
    if (i < BB) g_numpos[i] = 0;
    if (i == 0) { g_lossl = 0.0; g_lossc = 0.0; }
}

// ---------------- K1: matching ----------------
#define TPB1 256
#define PPT 4
#define PPB (TPB1 * PPT)                  // 1024 priors per block
#define NBLK_P ((PP + PPB - 1) / PPB)     // 9

__global__ void k1_match(const float* __restrict__ targets,
                         const float* __restrict__ priors) {
    const int b = blockIdx.y;
    const int base = blockIdx.x * PPB;
    const int tid = threadIdx.x;

    __shared__ float s_t[OO][5]; // x1,y1,x2,y2,area

    for (int i = tid; i < OO; i += TPB1) {
        const float* t = targets + ((size_t)b * OO + i) * 5;
        float x1 = t[0], y1 = t[1], x2 = t[2], y2 = t[3];
        s_t[i][0] = x1; s_t[i][1] = y1; s_t[i][2] = x2; s_t[i][3] = y2;
        s_t[i][4] = (x2 - x1) * (y2 - y1);
    }
    __syncthreads();

    // my priors (corner form + area), strided for coalescing
    float px1[PPT], py1[PPT], px2[PPT], py2[PPT], pa[PPT];
    int   pp[PPT];
    float bi[PPT], bu[PPT]; int bo[PPT]; // per-prior best truth (inter,union,o)
#pragma unroll
    for (int j = 0; j < PPT; j++) {
        int p = base + tid + j * TPB1;
        pp[j] = p;
        if (p < PP) {
            float4 pr = *(const float4*)(priors + (size_t)p * 4);
            float x1 = pr.x - pr.z * 0.5f, y1 = pr.y - pr.w * 0.5f;
            float x2 = pr.x + pr.z * 0.5f, y2 = pr.y + pr.w * 0.5f;
            px1[j] = x1; py1[j] = y1; px2[j] = x2; py2[j] = y2;
            pa[j] = (x2 - x1) * (y2 - y1);
        } else {
            px1[j] = 4e9f; py1[j] = 4e9f; px2[j] = 4e9f; py2[j] = 4e9f;
            pa[j] = 0.f;
        }
        bi[j] = -1.f; bu[j] = 1.f; bo[j] = 0;
    }

    for (int o = 0; o < OO; o++) {
        const float tx1 = s_t[o][0], ty1 = s_t[o][1];
        const float tx2 = s_t[o][2], ty2 = s_t[o][3];
        const float ta  = s_t[o][4];

        // thread-local best prior for this truth
        float ci = -1.f, cu = 1.f; int cp = INT_MAX;
#pragma unroll
        for (int j = 0; j < PPT; j++) {
            float lx = fmaxf(tx1, px1[j]), ly = fmaxf(ty1, py1[j]);
            float rx = fminf(tx2, px2[j]), ry = fminf(ty2, py2[j]);
            float w = fmaxf(rx - lx, 0.f), h = fmaxf(ry - ly, 0.f);
            float inter = w * h;
            float uni = ta + pa[j] - inter;
            // per-prior best truth (strict > keeps lowest o, matching argmax)
            if (inter * bu[j] > bi[j] * uni) { bi[j] = inter; bu[j] = uni; bo[j] = o; }
            // per-truth best prior (prefer lower p on exact tie)
            if (pp[j] < PP) {
                float l = inter * cu, r = ci * uni;
                if (l > r || (l == r && pp[j] < cp)) { ci = inter; cu = uni; cp = pp[j]; }
            }
        }
        // warp reduce (ci,cu,cp)
#pragma unroll
        for (int off = 16; off > 0; off >>= 1) {
            float oi = __shfl_down_sync(0xFFFFFFFFu, ci, off);
            float ou = __shfl_down_sync(0xFFFFFFFFu, cu, off);
            int   op = __shfl_down_sync(0xFFFFFFFFu, cp, off);
            float l = oi * cu, r = ci * ou;
            if (l > r || (l == r && op < cp)) { ci = oi; cu = ou; cp = op; }
        }
        if ((tid & 31) == 0 && cp != INT_MAX) {
            float ov = __fdiv_rn(ci, cu);
            unsigned long long key =
                ((unsigned long long)__float_as_uint(ov) << 32) |
                (unsigned long long)(0xFFFFFFFFu - (unsigned)cp);
            atomicMax(&g_bestprior[b * OO + o], key);
        }
    }

#pragma unroll
    for (int j = 0; j < PPT; j++) {
        if (pp[j] < PP) {
            float ov = __fdiv_rn(bi[j], bu[j]);
            g_bti[(size_t)b * PP + pp[j]] = bo[j];
            g_bto[(size_t)b * PP + pp[j]] = ov;
        }
    }
}

// ---------------- K2: force-match override (sequential last-wins) ----------------
__global__ void k2_override() {
    int b = threadIdx.x;
    if (b >= BB) return;
    for (int o = 0; o < OO; o++) {
        unsigned long long key = g_bestprior[b * OO + o];
        int p = (int)(0xFFFFFFFFu - (unsigned)(key & 0xFFFFFFFFull));
        g_bto[(size_t)b * PP + p] = 2.0f;
        g_bti[(size_t)b * PP + p] = o;
    }
}

// ---------------- K3: conf targets + loc loss ----------------
__device__ __forceinline__ float sl1(float d) {
    float a = fabsf(d);
    return (a < 1.f) ? 0.5f * a * a : (a - 0.5f);
}

__global__ void k3_pos(const float* __restrict__ loc,
                       const float* __restrict__ targets,
                       const float* __restrict__ priors) {
    const int b = blockIdx.y;
    const int p = blockIdx.x * blockDim.x + threadIdx.x;
    double ll = 0.0; int np = 0;
    if (p < PP) {
        const size_t idx = (size_t)b * PP + p;
        float ov = g_bto[idx];
        int o = g_bti[idx];
        const float* t = targets + ((size_t)b * OO + o) * 5;
        int conf = (ov < 0.5f) ? 0 : ((int)t[4] + 1);
        g_conft[idx] = conf;
        if (conf > 0) {
            np = 1;
            float4 pr = *(const float4*)(priors + (size_t)p * 4);
            float m0 = t[0], m1 = t[1], m2 = t[2], m3 = t[3];
            float gx = ((m0 + m2) * 0.5f - pr.x) / (0.1f * pr.z);
            float gy = ((m1 + m3) * 0.5f - pr.y) / (0.1f * pr.w);
            float gw = logf((m2 - m0) / pr.z) / 0.2f;
            float gh = logf((m3 - m1) / pr.w) / 0.2f;
            const float* L = loc + idx * 4;
            ll = (double)sl1(L[0] - gx) + (double)sl1(L[1] - gy)
               + (double)sl1(L[2] - gw) + (double)sl1(L[3] - gh);
        }
    }
#pragma unroll
    for (int off = 16; off > 0; off >>= 1) {
        ll += __shfl_down_sync(0xFFFFFFFFu, ll, off);
        np += __shfl_down_sync(0xFFFFFFFFu, np, off);
    }
    if ((threadIdx.x & 31) == 0) {
        if (ll != 0.0) atomicAdd(&g_lossl, ll);
        if (np) atomicAdd(&g_numpos[b], np);
    }
}

// ---------------- K4: per-prior cross entropy (warp per prior) ----------------
__global__ void k4_ce(const float* __restrict__ conf) {
    const int w = (blockIdx.x * blockDim.x + threadIdx.x) >> 5;
    const int lane = threadIdx.x & 31;
    if (w >= BB * PP) return;
    const float* x = conf + (size_t)w * CC;
    float x0 = x[lane];
    float x1 = x[lane + 32];
    float x2 = (lane < 17) ? x[lane + 64] : -3e38f;
    float m = fmaxf(fmaxf(x0, x1), x2);
#pragma unroll
    for (int off = 16; off > 0; off >>= 1)
        m = fmaxf(m, __shfl_xor_sync(0xFFFFFFFFu, m, off));
    float s = __expf(x0 - m) + __expf(x1 - m) + ((lane < 17) ? __expf(x2 - m) : 0.f);
#pragma unroll
    for (int off = 16; off > 0; off >>= 1)
        s += __shfl_xor_sync(0xFFFFFFFFu, s, off);
    int t = g_conft[w];
    float xt = (lane == t) ? x0 : ((lane + 32 == t) ? x1 : ((lane + 64 == t) ? x2 : 0.f));
#pragma unroll
    for (int off = 16; off > 0; off >>= 1)
        xt += __shfl_xor_sync(0xFFFFFFFFu, xt, off);
    if (lane == 0) {
        float ce = __logf(s) + m - xt;
        if (t > 0) {
            atomicAdd(&g_lossc, (double)ce);
            g_cerank[w] = 0.f;
        } else {
            g_cerank[w] = ce;
        }
    }
}

// ---------------- K5: hard-negative mining (exact radix top-k sum) ----------------
__global__ void k5_mine() {
    __shared__ unsigned sk[PP];
    __shared__ int cnt_s;
    __shared__ double sum_s;
    __shared__ int cg_s;

    const int b = blockIdx.x;
    const int tid = threadIdx.x;
    const int T = blockDim.x;

    for (int i = tid; i < PP; i += T)
        sk[i] = __float_as_uint(g_cerank[(size_t)b * PP + i]);
    int np = g_numpos[b];
    int k = min(3 * np, PP - 1);
    if (tid == 0) { sum_s = 0.0; cg_s = 0; }
    __syncthreads();
    if (k <= 0) return;

    unsigned prefix = 0;
    int kk = k;
    for (int bit = 31; bit >= 0; bit--) {
        if (tid == 0) cnt_s = 0;
        __syncthreads();
        unsigned want = (prefix | (1u << bit)) >> bit;
        int c = 0;
        for (int i = tid; i < PP; i += T) c += ((sk[i] >> bit) == want);
#pragma unroll
        for (int off = 16; off > 0; off >>= 1)
            c += __shfl_down_sync(0xFFFFFFFFu, c, off);
        if ((tid & 31) == 0 && c) atomicAdd(&cnt_s, c);
        __syncthreads();
        int cnt = cnt_s;
        if (cnt >= kk) prefix |= (1u << bit); else kk -= cnt;
        __syncthreads();
    }

    const unsigned T0 = prefix; // value of k-th largest key (exact)
    double s = 0.0; int cg = 0;
    for (int i = tid; i < PP; i += T) {
        unsigned key = sk[i];
        if (key > T0) { s += (double)__uint_as_float(key); cg++; }
    }
#pragma unroll
    for (int off = 16; off > 0; off >>= 1) {
        s += __shfl_down_sync(0xFFFFFFFFu, s, off);
        cg += __shfl_down_sync(0xFFFFFFFFu, cg, off);
    }
    if ((tid & 31) == 0) {
        if (s != 0.0) atomicAdd(&sum_s, s);
        if (cg) atomicAdd(&cg_s, cg);
    }
    __syncthreads();
    if (tid == 0) {
        double total = sum_s + (double)(k - cg_s) * (double)__uint_as_float(T0);
        atomicAdd(&g_lossc, total);
    }
}

// ---------------- K6: finalize ----------------
__global__ void k6_final(float* __restrict__ out) {
    int N = 0;
    for (int b = 0; b < BB; b++) N += g_numpos[b];
    double Nd = (double)N;
    out[0] = (float)(g_lossl / Nd);
    out[1] = (float)(g_lossc / Nd);
}

// ---------------- launch ----------------
extern "C" void kernel_launch(void* const* d_in, const int* in_sizes, int n_in,
                              void* d_out, int out_size) {
    const float* loc     = (const float*)d_in[0];
    const float* conf    = (const float*)d_in[1];
    const float* targets = (const float*)d_in[2];
    const float* priors  = (const float*)d_in[3];
    float* out = (float*)d_out;

    k0_zero<<<(BB * OO + 255) / 256, 256>>>();

    dim3 g1(NBLK_P, BB);
    k1_match<<<g1, TPB1>>>(targets, priors);

    k2_override<<<1, BB>>>();

    dim3 g3((PP + 255) / 256, BB);
    k3_pos<<<g3, 256>>>(loc, targets, priors);

    k4_ce<<<(BB * PP + 7) / 8, 256>>>(conf);

    k5_mine<<<BB, 1024>>>();

    k6_final<<<1, 1>>>(out);
}